// round 1
// baseline (speedup 1.0000x reference)
#include <cuda_runtime.h>
#include <cstddef>

// ---------------------------------------------------------------------------
// Problem constants: B=16, S=1024, DIM=768, H=12, HEAD_DIM=64
// qkv buffer: [B, S, 3*DIM] fp32; attn buffer: [B, S, DIM] fp32
// ---------------------------------------------------------------------------
#define BATCH 16
#define SEQ   1024
#define DIM   768
#define NH    12
#define HD    64

__device__ float g_qkv[BATCH * SEQ * 3 * DIM];   // 151 MB scratch
__device__ float g_attn[BATCH * SEQ * DIM];      // 48 MB scratch

// ---------------------------------------------------------------------------
// SGEMM: C[M,N] = A[M,K] @ B[K,N] + bias[N]
// 128x128 block tile, BK=8, 256 threads, 8x8 per-thread micro-tile.
// All dims divide evenly for this problem (no bounds checks).
// ---------------------------------------------------------------------------
__global__ __launch_bounds__(256) void sgemm_bias(
    const float* __restrict__ A, const float* __restrict__ B,
    const float* __restrict__ bias, float* __restrict__ C,
    int M, int N, int K)
{
    __shared__ float As[8][132];   // transposed A tile, padded
    __shared__ float Bs[8][132];

    const int t  = threadIdx.x;
    const int bm = blockIdx.y * 128;
    const int bn = blockIdx.x * 128;

    const int arow = t >> 1;            // 0..127
    const int acol = (t & 1) * 4;       // 0 or 4
    const int brow = t >> 5;            // 0..7
    const int bcol = (t & 31) * 4;      // 0..124
    const int ty   = t >> 4;            // 0..15
    const int tx   = t & 15;            // 0..15

    const float* Ap = A + (size_t)(bm + arow) * K + acol;
    const float* Bp = B + (size_t)brow * N + bn + bcol;

    float acc[8][8];
    #pragma unroll
    for (int i = 0; i < 8; i++)
        #pragma unroll
        for (int j = 0; j < 8; j++) acc[i][j] = 0.f;

    for (int k0 = 0; k0 < K; k0 += 8) {
        float4 av = *(const float4*)(Ap + k0);
        float4 bv = *(const float4*)(Bp + (size_t)k0 * N);
        As[acol + 0][arow] = av.x;
        As[acol + 1][arow] = av.y;
        As[acol + 2][arow] = av.z;
        As[acol + 3][arow] = av.w;
        *(float4*)&Bs[brow][bcol] = bv;
        __syncthreads();

        #pragma unroll
        for (int k = 0; k < 8; k++) {
            float a[8], b[8];
            *(float4*)&a[0] = *(const float4*)&As[k][ty * 8];
            *(float4*)&a[4] = *(const float4*)&As[k][ty * 8 + 4];
            *(float4*)&b[0] = *(const float4*)&Bs[k][tx * 8];
            *(float4*)&b[4] = *(const float4*)&Bs[k][tx * 8 + 4];
            #pragma unroll
            for (int i = 0; i < 8; i++)
                #pragma unroll
                for (int j = 0; j < 8; j++)
                    acc[i][j] = fmaf(a[i], b[j], acc[i][j]);
        }
        __syncthreads();
    }

    #pragma unroll
    for (int i = 0; i < 8; i++) {
        const size_t row = (size_t)(bm + ty * 8 + i);
        #pragma unroll
        for (int j = 0; j < 8; j += 4) {
            const int col = bn + tx * 8 + j;
            float4 o;
            o.x = acc[i][j + 0] + bias[col + 0];
            o.y = acc[i][j + 1] + bias[col + 1];
            o.z = acc[i][j + 2] + bias[col + 2];
            o.w = acc[i][j + 3] + bias[col + 3];
            *(float4*)&C[row * N + col] = o;
        }
    }
}

// ---------------------------------------------------------------------------
// Causal flash-attention over qkv buffer.
// Grid: (qtile=16, head=12, batch=16). Block: 128 threads.
// Q tile = 64 rows. Per-thread micro-tile: 8 rows x 4 cols.
// smem: QsT[64d][68r], KsT[64d][68c], Vs[64k][68d], PsT[64c][65r]
// ---------------------------------------------------------------------------
#define QSTRIDE 68
#define PSTRIDE 65
#define ATT_SMEM_FLOATS (3 * 64 * QSTRIDE + 64 * PSTRIDE)

__global__ __launch_bounds__(128) void attn_kernel(
    const float* __restrict__ qkv, float* __restrict__ out)
{
    extern __shared__ float sm[];
    float* QsT = sm;                       // [d][r]
    float* KsT = QsT + 64 * QSTRIDE;       // [d][c]
    float* Vs  = KsT + 64 * QSTRIDE;       // [k][d]
    float* PsT = Vs  + 64 * QSTRIDE;       // [c][r]

    const int qt = blockIdx.x;
    const int h  = blockIdx.y;
    const int b  = blockIdx.z;
    const int t  = threadIdx.x;
    const int ty = t >> 4, tx = t & 15;
    const int r0 = ty * 8, c0 = tx * 4;
    const int lrow  = t >> 1;          // 0..63
    const int lhalf = (t & 1) * 32;    // 0 or 32

    // ---- load Q tile (transposed into QsT) ----
    {
        const float* qb = qkv + ((size_t)(b * SEQ + qt * 64 + lrow) * (3 * DIM))
                        + h * HD + lhalf;
        float reg[32];
        #pragma unroll
        for (int i = 0; i < 8; i++)
            *(float4*)&reg[i * 4] = *(const float4*)(qb + i * 4);
        #pragma unroll
        for (int j = 0; j < 32; j++)
            QsT[(lhalf + j) * QSTRIDE + lrow] = reg[j];
    }

    float m[8], l[8], acc[8][4];
    #pragma unroll
    for (int i = 0; i < 8; i++) {
        m[i] = -1e30f; l[i] = 0.f;
        #pragma unroll
        for (int j = 0; j < 4; j++) acc[i][j] = 0.f;
    }

    for (int jt = 0; jt <= qt; jt++) {
        __syncthreads();  // previous iteration's consumers done (also covers Q load)

        // ---- load K tile (transposed) and V tile ----
        {
            const float* kb = qkv + ((size_t)(b * SEQ + jt * 64 + lrow) * (3 * DIM))
                            + DIM + h * HD + lhalf;
            float reg[32];
            #pragma unroll
            for (int i = 0; i < 8; i++)
                *(float4*)&reg[i * 4] = *(const float4*)(kb + i * 4);
            #pragma unroll
            for (int j = 0; j < 32; j++)
                KsT[(lhalf + j) * QSTRIDE + lrow] = reg[j];

            const float* vb = kb + DIM;   // v is DIM further along
            #pragma unroll
            for (int i = 0; i < 8; i++) {
                float4 vv = *(const float4*)(vb + i * 4);
                *(float4*)&Vs[lrow * QSTRIDE + lhalf + i * 4] = vv;
            }
        }
        __syncthreads();

        // ---- scores: s = Q @ K^T (8x4 per thread) ----
        float s[8][4];
        #pragma unroll
        for (int i = 0; i < 8; i++)
            #pragma unroll
            for (int j = 0; j < 4; j++) s[i][j] = 0.f;

        #pragma unroll 4
        for (int d = 0; d < HD; d++) {
            float a[8], bb[4];
            *(float4*)&a[0]  = *(const float4*)&QsT[d * QSTRIDE + r0];
            *(float4*)&a[4]  = *(const float4*)&QsT[d * QSTRIDE + r0 + 4];
            *(float4*)&bb[0] = *(const float4*)&KsT[d * QSTRIDE + c0];
            #pragma unroll
            for (int i = 0; i < 8; i++)
                #pragma unroll
                for (int j = 0; j < 4; j++)
                    s[i][j] = fmaf(a[i], bb[j], s[i][j]);
        }

        // ---- scale + causal mask (diagonal tile only) ----
        const bool diag = (jt == qt);
        #pragma unroll
        for (int i = 0; i < 8; i++)
            #pragma unroll
            for (int j = 0; j < 4; j++) {
                float v = s[i][j] * 0.125f;   // 1/sqrt(64)
                if (diag && (c0 + j > r0 + i)) v = -1e30f;
                s[i][j] = v;
            }

        // ---- online softmax update ----
        #pragma unroll
        for (int i = 0; i < 8; i++) {
            float tmax = fmaxf(fmaxf(s[i][0], s[i][1]), fmaxf(s[i][2], s[i][3]));
            #pragma unroll
            for (int off = 8; off > 0; off >>= 1)
                tmax = fmaxf(tmax, __shfl_xor_sync(0xffffffffu, tmax, off));
            const float mn   = fmaxf(m[i], tmax);
            const float corr = __expf(m[i] - mn);
            m[i] = mn;
            float rs = 0.f;
            #pragma unroll
            for (int j = 0; j < 4; j++) {
                float p = __expf(s[i][j] - mn);
                s[i][j] = p;
                rs += p;
            }
            #pragma unroll
            for (int off = 8; off > 0; off >>= 1)
                rs += __shfl_xor_sync(0xffffffffu, rs, off);
            l[i] = l[i] * corr + rs;
            #pragma unroll
            for (int j = 0; j < 4; j++) acc[i][j] *= corr;
        }

        // ---- write P (transposed) ----
        #pragma unroll
        for (int i = 0; i < 8; i++)
            #pragma unroll
            for (int j = 0; j < 4; j++)
                PsT[(c0 + j) * PSTRIDE + r0 + i] = s[i][j];
        __syncthreads();

        // ---- O += P @ V ----
        #pragma unroll 4
        for (int k = 0; k < 64; k++) {
            float vv[4];
            *(float4*)&vv[0] = *(const float4*)&Vs[k * QSTRIDE + c0];
            #pragma unroll
            for (int i = 0; i < 8; i++) {
                const float p = PsT[k * PSTRIDE + r0 + i];
                #pragma unroll
                for (int j = 0; j < 4; j++)
                    acc[i][j] = fmaf(p, vv[j], acc[i][j]);
            }
        }
    }

    // ---- normalize + write out ----
    #pragma unroll
    for (int i = 0; i < 8; i++) {
        const float inv = 1.f / l[i];
        float4 o;
        o.x = acc[i][0] * inv;
        o.y = acc[i][1] * inv;
        o.z = acc[i][2] * inv;
        o.w = acc[i][3] * inv;
        const size_t row = (size_t)(b * SEQ + qt * 64 + r0 + i);
        *(float4*)&out[row * DIM + h * HD + c0] = o;
    }
}

// ---------------------------------------------------------------------------
// Launch: qkv GEMM -> flash attention -> proj GEMM
// ---------------------------------------------------------------------------
extern "C" void kernel_launch(void* const* d_in, const int* in_sizes, int n_in,
                              void* d_out, int out_size)
{
    const float* x      = (const float*)d_in[0];
    const float* W_attn = (const float*)d_in[1];
    const float* b_attn = (const float*)d_in[2];
    const float* W_proj = (const float*)d_in[3];
    const float* b_proj = (const float*)d_in[4];
    float* out = (float*)d_out;

    float *qkv, *attn;
    cudaGetSymbolAddress((void**)&qkv,  g_qkv);
    cudaGetSymbolAddress((void**)&attn, g_attn);

    const int M = BATCH * SEQ;   // 16384

    // 1) qkv = x @ W_attn + b_attn   [M x 2304]
    {
        dim3 grid((3 * DIM) / 128, M / 128);
        sgemm_bias<<<grid, 256>>>(x, W_attn, b_attn, qkv, M, 3 * DIM, DIM);
    }

    // 2) causal multi-head attention -> attn [M x 768]
    {
        const size_t smem = ATT_SMEM_FLOATS * sizeof(float);   // 68864 B
        cudaFuncSetAttribute(attn_kernel,
                             cudaFuncAttributeMaxDynamicSharedMemorySize,
                             (int)smem);
        dim3 grid(SEQ / 64, NH, BATCH);
        attn_kernel<<<grid, 128, smem>>>(qkv, attn);
    }

    // 3) out = attn @ W_proj + b_proj  [M x 768]
    {
        dim3 grid(DIM / 128, M / 128);
        sgemm_bias<<<grid, 256>>>(attn, W_proj, b_proj, out, M, DIM, DIM);
    }
}

// round 3
// speedup vs baseline: 1.7442x; 1.7442x over previous
#include <cuda_runtime.h>
#include <cuda_bf16.h>
#include <cstdint>
#include <cstddef>

// ---------------------------------------------------------------------------
// B=16, S=1024, DIM=768, H=12, HD=64
//   qkv  = x @ W_attn + b_attn     [16384, 2304]   (HMMA bf16 hi/lo, fp32 out)
//   attn = causal_mha(qkv)         [16384, 768]    (fp32 SIMT, emits bf16 hi/lo)
//   out  = attn @ W_proj + b_proj  [16384, 768]    (HMMA bf16 hi/lo)
// ---------------------------------------------------------------------------
#define BATCH 16
#define SEQ   1024
#define DIM   768
#define NH    12
#define HD    64
#define MROWS (BATCH * SEQ)
#define KTOT  768
#define N1    (3 * DIM)
#define N2    DIM

__device__ float          g_qkv[MROWS * N1];
__device__ __nv_bfloat16  g_xh[MROWS * KTOT];
__device__ __nv_bfloat16  g_xl[MROWS * KTOT];
__device__ __nv_bfloat16  g_ah[MROWS * KTOT];
__device__ __nv_bfloat16  g_al[MROWS * KTOT];
__device__ __nv_bfloat16  g_wth[N1 * KTOT];
__device__ __nv_bfloat16  g_wtl[N1 * KTOT];

// ============================ PTX helpers ==================================
__device__ __forceinline__ uint32_t smem_u32(const void* p) {
    uint32_t a;
    asm("{ .reg .u64 t; cvta.to.shared.u64 t, %1; cvt.u32.u64 %0, t; }"
        : "=r"(a) : "l"(p));
    return a;
}

#define CP16(d, s) \
    asm volatile("cp.async.cg.shared.global [%0], [%1], 16;" :: "r"(d), "l"(s))
#define CP_COMMIT() asm volatile("cp.async.commit_group;" ::: "memory")
#define CP_WAIT(n)  asm volatile("cp.async.wait_group %0;" :: "n"(n) : "memory")

#define LDSM4(r0, r1, r2, r3, a) \
    asm volatile("ldmatrix.sync.aligned.m8n8.x4.shared.b16 {%0,%1,%2,%3}, [%4];" \
                 : "=r"(r0), "=r"(r1), "=r"(r2), "=r"(r3) : "r"(a))

#define MMA_BF16(d, a, b) \
    asm volatile("mma.sync.aligned.m16n8k16.row.col.f32.bf16.bf16.f32 " \
                 "{%0,%1,%2,%3}, {%4,%5,%6,%7}, {%8,%9}, {%0,%1,%2,%3};" \
                 : "+f"((d)[0]), "+f"((d)[1]), "+f"((d)[2]), "+f"((d)[3]) \
                 : "r"((a)[0]), "r"((a)[1]), "r"((a)[2]), "r"((a)[3]), \
                   "r"((b)[0]), "r"((b)[1]))

// ======================= conversion kernels ================================
__global__ __launch_bounds__(256) void split_fp32(
    const float* __restrict__ in, __nv_bfloat16* __restrict__ hi,
    __nv_bfloat16* __restrict__ lo, int n4)
{
    int i = blockIdx.x * 256 + threadIdx.x;
    if (i >= n4) return;
    float4 v = ((const float4*)in)[i];
    __nv_bfloat16 h0 = __float2bfloat16(v.x), h1 = __float2bfloat16(v.y);
    __nv_bfloat16 h2 = __float2bfloat16(v.z), h3 = __float2bfloat16(v.w);
    __nv_bfloat16 l0 = __float2bfloat16(v.x - __bfloat162float(h0));
    __nv_bfloat16 l1 = __float2bfloat16(v.y - __bfloat162float(h1));
    __nv_bfloat16 l2 = __float2bfloat16(v.z - __bfloat162float(h2));
    __nv_bfloat16 l3 = __float2bfloat16(v.w - __bfloat162float(h3));
    __nv_bfloat162* hp = (__nv_bfloat162*)hi;
    __nv_bfloat162* lp = (__nv_bfloat162*)lo;
    hp[i * 2 + 0] = __nv_bfloat162(h0, h1);
    hp[i * 2 + 1] = __nv_bfloat162(h2, h3);
    lp[i * 2 + 0] = __nv_bfloat162(l0, l1);
    lp[i * 2 + 1] = __nv_bfloat162(l2, l3);
}

__global__ __launch_bounds__(256) void transpose_split(
    const float* __restrict__ W, __nv_bfloat16* __restrict__ Th,
    __nv_bfloat16* __restrict__ Tl, int K, int N)
{
    __shared__ float tile[32][33];
    int tx = threadIdx.x, ty = threadIdx.y;
    int nx = blockIdx.x * 32 + tx;
    int ky = blockIdx.y * 32 + ty;
    #pragma unroll
    for (int j = 0; j < 32; j += 8)
        tile[ty + j][tx] = W[(size_t)(ky + j) * N + nx];
    __syncthreads();
    int kx = blockIdx.y * 32 + tx;
    int ny = blockIdx.x * 32 + ty;
    #pragma unroll
    for (int j = 0; j < 32; j += 8) {
        float v = tile[tx][ty + j];
        __nv_bfloat16 h = __float2bfloat16(v);
        __nv_bfloat16 l = __float2bfloat16(v - __bfloat162float(h));
        Th[(size_t)(ny + j) * K + kx] = h;
        Tl[(size_t)(ny + j) * K + kx] = l;
    }
}

// ===================== HMMA GEMM (bf16 hi/lo x3) ===========================
// C[M,Ntot] = (Ah+Al)[M,768] @ (Bh+Bl)[Ntot,768]^T + bias
// 128x128 block, BK=64, 3 stages cp.async, 256 threads (8 warps, 32x64 each).
#define BK      64
#define NSTG    3
#define NIT     12                 // 768 / 64
#define T_AH    0
#define T_AL    16384
#define T_BH    32768
#define T_BL    49152
#define STG     65536
#define GEMM_SMEM (NSTG * STG)     // 196608

__device__ __forceinline__ void stage_load(
    uint32_t sstage,
    const __nv_bfloat16* Ah, const __nv_bfloat16* Al,
    const __nv_bfloat16* Bh, const __nv_bfloat16* Bl,
    int mtile, int ntile, int kiter, int tid)
{
    #pragma unroll
    for (int j = 0; j < 4; j++) {
        int cidx = tid + j * 256;         // 0..1023
        int r = cidx >> 3, c = cidx & 7;
        uint32_t so = (uint32_t)(r * 128 + (((c) ^ (r & 7)) << 4));
        size_t gA = (size_t)(mtile * 128 + r) * KTOT + kiter * BK + c * 8;
        size_t gB = (size_t)(ntile * 128 + r) * KTOT + kiter * BK + c * 8;
        CP16(sstage + T_AH + so, (const char*)(Ah + gA));
        CP16(sstage + T_AL + so, (const char*)(Al + gA));
        CP16(sstage + T_BH + so, (const char*)(Bh + gB));
        CP16(sstage + T_BL + so, (const char*)(Bl + gB));
    }
}

__global__ __launch_bounds__(256) void gemm_mma(
    const __nv_bfloat16* __restrict__ Ah, const __nv_bfloat16* __restrict__ Al,
    const __nv_bfloat16* __restrict__ Bh, const __nv_bfloat16* __restrict__ Bl,
    const float* __restrict__ bias, float* __restrict__ C, int Ntot)
{
    extern __shared__ char smem[];
    const uint32_t sb = smem_u32(smem);
    const int tid = threadIdx.x, lane = tid & 31, wid = tid >> 5;
    const int mtile = blockIdx.y, ntile = blockIdx.x;
    const int wm = (wid & 3) * 32;        // warp m offset in tile
    const int wn = (wid >> 2) * 64;       // warp n offset in tile

    // per-lane ldmatrix row bases
    const int rowA  = wm + (lane & 15);                       // + mf*16
    const int xorA  = rowA & 7;
    const int clA   = lane >> 4;                              // chunk sel
    const int rowB  = wn + ((lane >> 4) << 3) + (lane & 7);   // + nf2*16
    const int xorB  = rowB & 7;
    const int clB   = (lane >> 3) & 1;

    float acc[2][8][4];
    #pragma unroll
    for (int mf = 0; mf < 2; mf++)
        #pragma unroll
        for (int nf = 0; nf < 8; nf++)
            #pragma unroll
            for (int q = 0; q < 4; q++) acc[mf][nf][q] = 0.f;

    stage_load(sb + 0 * STG, Ah, Al, Bh, Bl, mtile, ntile, 0, tid); CP_COMMIT();
    stage_load(sb + 1 * STG, Ah, Al, Bh, Bl, mtile, ntile, 1, tid); CP_COMMIT();

    for (int i = 0; i < NIT; i++) {
        if (i + 2 < NIT) {
            stage_load(sb + ((i + 2) % NSTG) * STG, Ah, Al, Bh, Bl,
                       mtile, ntile, i + 2, tid);
            CP_COMMIT();
            CP_WAIT(2);
        } else if (i + 1 < NIT) {
            CP_WAIT(1);
        } else {
            CP_WAIT(0);
        }
        __syncthreads();

        const uint32_t st = sb + (i % NSTG) * STG;
        #pragma unroll
        for (int ks = 0; ks < 4; ks++) {
            uint32_t ah[2][4], al[2][4], bh[8][2], bl[8][2];
            #pragma unroll
            for (int mf = 0; mf < 2; mf++) {
                uint32_t off = (uint32_t)((rowA + mf * 16) * 128 +
                               ((((ks << 1) + clA) ^ xorA) << 4));
                LDSM4(ah[mf][0], ah[mf][1], ah[mf][2], ah[mf][3], st + T_AH + off);
                LDSM4(al[mf][0], al[mf][1], al[mf][2], al[mf][3], st + T_AL + off);
            }
            #pragma unroll
            for (int nf2 = 0; nf2 < 4; nf2++) {
                uint32_t off = (uint32_t)((rowB + nf2 * 16) * 128 +
                               ((((ks << 1) + clB) ^ xorB) << 4));
                LDSM4(bh[nf2 * 2][0], bh[nf2 * 2][1],
                      bh[nf2 * 2 + 1][0], bh[nf2 * 2 + 1][1], st + T_BH + off);
                LDSM4(bl[nf2 * 2][0], bl[nf2 * 2][1],
                      bl[nf2 * 2 + 1][0], bl[nf2 * 2 + 1][1], st + T_BL + off);
            }
            #pragma unroll
            for (int mf = 0; mf < 2; mf++)
                #pragma unroll
                for (int nf = 0; nf < 8; nf++) {
                    MMA_BF16(acc[mf][nf], ah[mf], bh[nf]);
                    MMA_BF16(acc[mf][nf], ah[mf], bl[nf]);
                    MMA_BF16(acc[mf][nf], al[mf], bh[nf]);
                }
        }
        __syncthreads();
    }

    // epilogue
    #pragma unroll
    for (int mf = 0; mf < 2; mf++) {
        #pragma unroll
        for (int nf = 0; nf < 8; nf++) {
            const int col = ntile * 128 + wn + nf * 8 + (lane & 3) * 2;
            const int row0 = mtile * 128 + wm + mf * 16 + (lane >> 2);
            const float b0 = bias[col], b1 = bias[col + 1];
            float2 v0 = make_float2(acc[mf][nf][0] + b0, acc[mf][nf][1] + b1);
            float2 v1 = make_float2(acc[mf][nf][2] + b0, acc[mf][nf][3] + b1);
            *(float2*)&C[(size_t)row0 * Ntot + col] = v0;
            *(float2*)&C[(size_t)(row0 + 8) * Ntot + col] = v1;
        }
    }
}

// ===================== causal flash attention (fp32 SIMT) ==================
#define QSTRIDE 68
#define PSTRIDE 65
#define ATT_SMEM_FLOATS (3 * 64 * QSTRIDE + 64 * PSTRIDE)

__global__ __launch_bounds__(128) void attn_kernel(
    const float* __restrict__ qkv,
    __nv_bfloat16* __restrict__ oh, __nv_bfloat16* __restrict__ ol)
{
    extern __shared__ float sm[];
    float* QsT = sm;
    float* KsT = QsT + 64 * QSTRIDE;
    float* Vs  = KsT + 64 * QSTRIDE;
    float* PsT = Vs  + 64 * QSTRIDE;

    const int qt = blockIdx.x, h = blockIdx.y, b = blockIdx.z;
    const int t = threadIdx.x;
    const int ty = t >> 4, tx = t & 15;
    const int r0 = ty * 8, c0 = tx * 4;
    const int lrow = t >> 1, lhalf = (t & 1) * 32;

    {
        const float* qb = qkv + ((size_t)(b * SEQ + qt * 64 + lrow) * N1) + h * HD + lhalf;
        float reg[32];
        #pragma unroll
        for (int i = 0; i < 8; i++) *(float4*)&reg[i * 4] = *(const float4*)(qb + i * 4);
        #pragma unroll
        for (int j = 0; j < 32; j++) QsT[(lhalf + j) * QSTRIDE + lrow] = reg[j];
    }

    float m[8], l[8], acc[8][4];
    #pragma unroll
    for (int i = 0; i < 8; i++) {
        m[i] = -1e30f; l[i] = 0.f;
        #pragma unroll
        for (int j = 0; j < 4; j++) acc[i][j] = 0.f;
    }

    for (int jt = 0; jt <= qt; jt++) {
        __syncthreads();
        {
            const float* kb = qkv + ((size_t)(b * SEQ + jt * 64 + lrow) * N1) + DIM + h * HD + lhalf;
            float reg[32];
            #pragma unroll
            for (int i = 0; i < 8; i++) *(float4*)&reg[i * 4] = *(const float4*)(kb + i * 4);
            #pragma unroll
            for (int j = 0; j < 32; j++) KsT[(lhalf + j) * QSTRIDE + lrow] = reg[j];
            const float* vb = kb + DIM;
            #pragma unroll
            for (int i = 0; i < 8; i++) {
                float4 vv = *(const float4*)(vb + i * 4);
                *(float4*)&Vs[lrow * QSTRIDE + lhalf + i * 4] = vv;
            }
        }
        __syncthreads();

        float s[8][4];
        #pragma unroll
        for (int i = 0; i < 8; i++)
            #pragma unroll
            for (int j = 0; j < 4; j++) s[i][j] = 0.f;

        #pragma unroll 4
        for (int d = 0; d < HD; d++) {
            float a[8], bb[4];
            *(float4*)&a[0]  = *(const float4*)&QsT[d * QSTRIDE + r0];
            *(float4*)&a[4]  = *(const float4*)&QsT[d * QSTRIDE + r0 + 4];
            *(float4*)&bb[0] = *(const float4*)&KsT[d * QSTRIDE + c0];
            #pragma unroll
            for (int i = 0; i < 8; i++)
                #pragma unroll
                for (int j = 0; j < 4; j++)
                    s[i][j] = fmaf(a[i], bb[j], s[i][j]);
        }

        const bool diag = (jt == qt);
        #pragma unroll
        for (int i = 0; i < 8; i++)
            #pragma unroll
            for (int j = 0; j < 4; j++) {
                float v = s[i][j] * 0.125f;
                if (diag && (c0 + j > r0 + i)) v = -1e30f;
                s[i][j] = v;
            }

        #pragma unroll
        for (int i = 0; i < 8; i++) {
            float tmax = fmaxf(fmaxf(s[i][0], s[i][1]), fmaxf(s[i][2], s[i][3]));
            #pragma unroll
            for (int off = 8; off > 0; off >>= 1)
                tmax = fmaxf(tmax, __shfl_xor_sync(0xffffffffu, tmax, off));
            const float mn = fmaxf(m[i], tmax);
            const float corr = __expf(m[i] - mn);
            m[i] = mn;
            float rs = 0.f;
            #pragma unroll
            for (int j = 0; j < 4; j++) {
                float p = __expf(s[i][j] - mn);
                s[i][j] = p;
                rs += p;
            }
            #pragma unroll
            for (int off = 8; off > 0; off >>= 1)
                rs += __shfl_xor_sync(0xffffffffu, rs, off);
            l[i] = l[i] * corr + rs;
            #pragma unroll
            for (int j = 0; j < 4; j++) acc[i][j] *= corr;
        }

        #pragma unroll
        for (int i = 0; i < 8; i++)
            #pragma unroll
            for (int j = 0; j < 4; j++)
                PsT[(c0 + j) * PSTRIDE + r0 + i] = s[i][j];
        __syncthreads();

        #pragma unroll 4
        for (int k = 0; k < 64; k++) {
            float vv[4];
            *(float4*)&vv[0] = *(const float4*)&Vs[k * QSTRIDE + c0];
            #pragma unroll
            for (int i = 0; i < 8; i++) {
                const float p = PsT[k * PSTRIDE + r0 + i];
                #pragma unroll
                for (int j = 0; j < 4; j++)
                    acc[i][j] = fmaf(p, vv[j], acc[i][j]);
            }
        }
    }

    #pragma unroll
    for (int i = 0; i < 8; i++) {
        const float inv = 1.f / l[i];
        const size_t off = (size_t)(b * SEQ + qt * 64 + r0 + i) * DIM + h * HD + c0;
        float v0 = acc[i][0] * inv, v1 = acc[i][1] * inv;
        float v2 = acc[i][2] * inv, v3 = acc[i][3] * inv;
        __nv_bfloat16 h0 = __float2bfloat16(v0), h1 = __float2bfloat16(v1);
        __nv_bfloat16 h2 = __float2bfloat16(v2), h3 = __float2bfloat16(v3);
        *(__nv_bfloat162*)&oh[off]     = __nv_bfloat162(h0, h1);
        *(__nv_bfloat162*)&oh[off + 2] = __nv_bfloat162(h2, h3);
        __nv_bfloat16 l0 = __float2bfloat16(v0 - __bfloat162float(h0));
        __nv_bfloat16 l1 = __float2bfloat16(v1 - __bfloat162float(h1));
        __nv_bfloat16 l2 = __float2bfloat16(v2 - __bfloat162float(h2));
        __nv_bfloat16 l3 = __float2bfloat16(v3 - __bfloat162float(h3));
        *(__nv_bfloat162*)&ol[off]     = __nv_bfloat162(l0, l1);
        *(__nv_bfloat162*)&ol[off + 2] = __nv_bfloat162(l2, l3);
    }
}

// =============================== launch ====================================
extern "C" void kernel_launch(void* const* d_in, const int* in_sizes, int n_in,
                              void* d_out, int out_size)
{
    const float* x      = (const float*)d_in[0];
    const float* W_attn = (const float*)d_in[1];
    const float* b_attn = (const float*)d_in[2];
    const float* W_proj = (const float*)d_in[3];
    const float* b_proj = (const float*)d_in[4];
    float* out = (float*)d_out;

    float *qkv;
    __nv_bfloat16 *xh, *xl, *ahp, *alp, *wth, *wtl;
    cudaGetSymbolAddress((void**)&qkv, g_qkv);
    cudaGetSymbolAddress((void**)&xh,  g_xh);
    cudaGetSymbolAddress((void**)&xl,  g_xl);
    cudaGetSymbolAddress((void**)&ahp, g_ah);
    cudaGetSymbolAddress((void**)&alp, g_al);
    cudaGetSymbolAddress((void**)&wth, g_wth);
    cudaGetSymbolAddress((void**)&wtl, g_wtl);

    static int attrs_set = 0;
    if (!attrs_set) {
        cudaFuncSetAttribute(gemm_mma, cudaFuncAttributeMaxDynamicSharedMemorySize,
                             GEMM_SMEM);
        cudaFuncSetAttribute(attn_kernel, cudaFuncAttributeMaxDynamicSharedMemorySize,
                             (int)(ATT_SMEM_FLOATS * sizeof(float)));
        attrs_set = 1;
    }

    // 1) split x -> bf16 hi/lo
    {
        int n4 = MROWS * KTOT / 4;
        split_fp32<<<(n4 + 255) / 256, 256>>>(x, xh, xl, n4);
    }
    // 2) W_attn [768,2304] -> transposed hi/lo [2304,768]
    transpose_split<<<dim3(N1 / 32, KTOT / 32), dim3(32, 8)>>>(W_attn, wth, wtl, KTOT, N1);
    // 3) qkv GEMM
    gemm_mma<<<dim3(N1 / 128, MROWS / 128), 256, GEMM_SMEM>>>(
        xh, xl, wth, wtl, b_attn, qkv, N1);
    // 4) attention
    attn_kernel<<<dim3(SEQ / 64, NH, BATCH), 128, ATT_SMEM_FLOATS * sizeof(float)>>>(
        qkv, ahp, alp);
    // 5) W_proj transpose/split
    transpose_split<<<dim3(N2 / 32, KTOT / 32), dim3(32, 8)>>>(W_proj, wth, wtl, KTOT, N2);
    // 6) out GEMM
    gemm_mma<<<dim3(N2 / 128, MROWS / 128), 256, GEMM_SMEM>>>(
        ahp, alp, wth, wtl, b_proj, out, N2);
}

// round 4
// speedup vs baseline: 2.8122x; 1.6123x over previous
#include <cuda_runtime.h>
#include <cuda_bf16.h>
#include <cstdint>
#include <cstddef>

// ---------------------------------------------------------------------------
// B=16, S=1024, DIM=768, H=12, HD=64
//   qkv(hi/lo bf16) = x @ W_attn + b_attn      (HMMA hi/lo x3)
//   attn            = causal MHA on tensor cores (HMMA hi/lo x3, online softmax)
//   out             = attn @ W_proj + b_proj    (HMMA hi/lo x3, fp32 out)
// ---------------------------------------------------------------------------
#define BATCH 16
#define SEQ   1024
#define DIM   768
#define NH    12
#define HD    64
#define MROWS (BATCH * SEQ)
#define KTOT  768
#define N1    (3 * DIM)
#define N2    DIM

__device__ __nv_bfloat16  g_qkvh[MROWS * N1];
__device__ __nv_bfloat16  g_qkvl[MROWS * N1];
__device__ __nv_bfloat16  g_vth[BATCH * NH * HD * SEQ];
__device__ __nv_bfloat16  g_vtl[BATCH * NH * HD * SEQ];
__device__ __nv_bfloat16  g_xh[MROWS * KTOT];
__device__ __nv_bfloat16  g_xl[MROWS * KTOT];
__device__ __nv_bfloat16  g_ah[MROWS * KTOT];
__device__ __nv_bfloat16  g_al[MROWS * KTOT];
__device__ __nv_bfloat16  g_wth[N1 * KTOT];
__device__ __nv_bfloat16  g_wtl[N1 * KTOT];

// ============================ PTX helpers ==================================
__device__ __forceinline__ uint32_t smem_u32(const void* p) {
    uint32_t a;
    asm("{ .reg .u64 t; cvta.to.shared.u64 t, %1; cvt.u32.u64 %0, t; }"
        : "=r"(a) : "l"(p));
    return a;
}

#define CP16(d, s) \
    asm volatile("cp.async.cg.shared.global [%0], [%1], 16;" :: "r"(d), "l"(s))
#define CP_COMMIT() asm volatile("cp.async.commit_group;" ::: "memory")
#define CP_WAIT(n)  asm volatile("cp.async.wait_group %0;" :: "n"(n) : "memory")

#define LDSM4(r0, r1, r2, r3, a) \
    asm volatile("ldmatrix.sync.aligned.m8n8.x4.shared.b16 {%0,%1,%2,%3}, [%4];" \
                 : "=r"(r0), "=r"(r1), "=r"(r2), "=r"(r3) : "r"(a))

#define MMA_BF16(d, a0, a1, a2, a3, b0, b1) \
    asm volatile("mma.sync.aligned.m16n8k16.row.col.f32.bf16.bf16.f32 " \
                 "{%0,%1,%2,%3}, {%4,%5,%6,%7}, {%8,%9}, {%0,%1,%2,%3};" \
                 : "+f"((d)[0]), "+f"((d)[1]), "+f"((d)[2]), "+f"((d)[3]) \
                 : "r"(a0), "r"(a1), "r"(a2), "r"(a3), "r"(b0), "r"(b1))

__device__ __forceinline__ void pack_hl(float x, float y, uint32_t& h, uint32_t& l) {
    __nv_bfloat162 hb = __float22bfloat162_rn(make_float2(x, y));
    float2 hf = __bfloat1622float2(hb);
    __nv_bfloat162 lb = __float22bfloat162_rn(make_float2(x - hf.x, y - hf.y));
    h = *(uint32_t*)&hb;
    l = *(uint32_t*)&lb;
}

// ======================= conversion kernels ================================
__global__ __launch_bounds__(256) void split_fp32(
    const float* __restrict__ in, __nv_bfloat16* __restrict__ hi,
    __nv_bfloat16* __restrict__ lo, int n4)
{
    int i = blockIdx.x * 256 + threadIdx.x;
    if (i >= n4) return;
    float4 v = ((const float4*)in)[i];
    uint32_t h0, l0, h1, l1;
    pack_hl(v.x, v.y, h0, l0);
    pack_hl(v.z, v.w, h1, l1);
    ((uint32_t*)hi)[i * 2 + 0] = h0;
    ((uint32_t*)hi)[i * 2 + 1] = h1;
    ((uint32_t*)lo)[i * 2 + 0] = l0;
    ((uint32_t*)lo)[i * 2 + 1] = l1;
}

__global__ __launch_bounds__(256) void transpose_split(
    const float* __restrict__ W, __nv_bfloat16* __restrict__ Th,
    __nv_bfloat16* __restrict__ Tl, int K, int N)
{
    __shared__ float tile[32][33];
    int tx = threadIdx.x, ty = threadIdx.y;
    int nx = blockIdx.x * 32 + tx;
    int ky = blockIdx.y * 32 + ty;
    #pragma unroll
    for (int j = 0; j < 32; j += 8)
        tile[ty + j][tx] = W[(size_t)(ky + j) * N + nx];
    __syncthreads();
    int kx = blockIdx.y * 32 + tx;
    int ny = blockIdx.x * 32 + ty;
    #pragma unroll
    for (int j = 0; j < 32; j += 8) {
        float v = tile[tx][ty + j];
        __nv_bfloat16 h = __float2bfloat16(v);
        __nv_bfloat16 l = __float2bfloat16(v - __bfloat162float(h));
        Th[(size_t)(ny + j) * K + kx] = h;
        Tl[(size_t)(ny + j) * K + kx] = l;
    }
}

// V part of qkv (hi/lo) -> transposed [b*NH+h][d][k] hi/lo
__global__ __launch_bounds__(256) void vtrans(
    const __nv_bfloat16* __restrict__ qh, const __nv_bfloat16* __restrict__ ql,
    __nv_bfloat16* __restrict__ vh, __nv_bfloat16* __restrict__ vl)
{
    __shared__ __nv_bfloat16 th[32][33], tl[32][33];
    const int bh = blockIdx.z;
    const int b = bh / NH, h = bh % NH;
    const int kk = blockIdx.x * 32, dd = blockIdx.y * 32;
    const int tx = threadIdx.x, ty = threadIdx.y;
    #pragma unroll
    for (int j = 0; j < 32; j += 8) {
        size_t src = (size_t)(b * SEQ + kk + ty + j) * N1 + 2 * DIM + h * HD + dd + tx;
        th[ty + j][tx] = qh[src];
        tl[ty + j][tx] = ql[src];
    }
    __syncthreads();
    #pragma unroll
    for (int j = 0; j < 32; j += 8) {
        size_t dst = (size_t)(bh * HD + dd + ty + j) * SEQ + kk + tx;
        vh[dst] = th[tx][ty + j];
        vl[dst] = tl[tx][ty + j];
    }
}

// ===================== HMMA GEMM (bf16 hi/lo x3) ===========================
#define BK      64
#define NSTG    3
#define NIT     12
#define T_AH    0
#define T_AL    16384
#define T_BH    32768
#define T_BL    49152
#define STG     65536
#define GEMM_SMEM (NSTG * STG)

__device__ __forceinline__ void stage_load(
    uint32_t sstage,
    const __nv_bfloat16* Ah, const __nv_bfloat16* Al,
    const __nv_bfloat16* Bh, const __nv_bfloat16* Bl,
    int mtile, int ntile, int kiter, int tid)
{
    #pragma unroll
    for (int j = 0; j < 4; j++) {
        int cidx = tid + j * 256;
        int r = cidx >> 3, c = cidx & 7;
        uint32_t so = (uint32_t)(r * 128 + (((c) ^ (r & 7)) << 4));
        size_t gA = (size_t)(mtile * 128 + r) * KTOT + kiter * BK + c * 8;
        size_t gB = (size_t)(ntile * 128 + r) * KTOT + kiter * BK + c * 8;
        CP16(sstage + T_AH + so, (const char*)(Ah + gA));
        CP16(sstage + T_AL + so, (const char*)(Al + gA));
        CP16(sstage + T_BH + so, (const char*)(Bh + gB));
        CP16(sstage + T_BL + so, (const char*)(Bl + gB));
    }
}

template<int OUTHL>
__global__ __launch_bounds__(256) void gemm_mma(
    const __nv_bfloat16* __restrict__ Ah, const __nv_bfloat16* __restrict__ Al,
    const __nv_bfloat16* __restrict__ Bh, const __nv_bfloat16* __restrict__ Bl,
    const float* __restrict__ bias, float* __restrict__ Cf,
    __nv_bfloat16* __restrict__ Ch, __nv_bfloat16* __restrict__ Cl, int Ntot)
{
    extern __shared__ char smem[];
    const uint32_t sb = smem_u32(smem);
    const int tid = threadIdx.x, lane = tid & 31, wid = tid >> 5;
    const int mtile = blockIdx.y, ntile = blockIdx.x;
    const int wm = (wid & 3) * 32;
    const int wn = (wid >> 2) * 64;

    const int rowA  = wm + (lane & 15);
    const int xorA  = rowA & 7;
    const int clA   = lane >> 4;
    const int rowB  = wn + ((lane >> 4) << 3) + (lane & 7);
    const int xorB  = rowB & 7;
    const int clB   = (lane >> 3) & 1;

    float acc[2][8][4];
    #pragma unroll
    for (int mf = 0; mf < 2; mf++)
        #pragma unroll
        for (int nf = 0; nf < 8; nf++)
            #pragma unroll
            for (int q = 0; q < 4; q++) acc[mf][nf][q] = 0.f;

    stage_load(sb + 0 * STG, Ah, Al, Bh, Bl, mtile, ntile, 0, tid); CP_COMMIT();
    stage_load(sb + 1 * STG, Ah, Al, Bh, Bl, mtile, ntile, 1, tid); CP_COMMIT();

    for (int i = 0; i < NIT; i++) {
        if (i + 2 < NIT) {
            stage_load(sb + ((i + 2) % NSTG) * STG, Ah, Al, Bh, Bl,
                       mtile, ntile, i + 2, tid);
            CP_COMMIT();
            CP_WAIT(2);
        } else if (i + 1 < NIT) {
            CP_WAIT(1);
        } else {
            CP_WAIT(0);
        }
        __syncthreads();

        const uint32_t st = sb + (i % NSTG) * STG;
        #pragma unroll
        for (int ks = 0; ks < 4; ks++) {
            uint32_t ah[2][4], al[2][4], bh[8][2], bl[8][2];
            #pragma unroll
            for (int mf = 0; mf < 2; mf++) {
                uint32_t off = (uint32_t)((rowA + mf * 16) * 128 +
                               ((((ks << 1) + clA) ^ xorA) << 4));
                LDSM4(ah[mf][0], ah[mf][1], ah[mf][2], ah[mf][3], st + T_AH + off);
                LDSM4(al[mf][0], al[mf][1], al[mf][2], al[mf][3], st + T_AL + off);
            }
            #pragma unroll
            for (int nf2 = 0; nf2 < 4; nf2++) {
                uint32_t off = (uint32_t)((rowB + nf2 * 16) * 128 +
                               ((((ks << 1) + clB) ^ xorB) << 4));
                LDSM4(bh[nf2 * 2][0], bh[nf2 * 2][1],
                      bh[nf2 * 2 + 1][0], bh[nf2 * 2 + 1][1], st + T_BH + off);
                LDSM4(bl[nf2 * 2][0], bl[nf2 * 2][1],
                      bl[nf2 * 2 + 1][0], bl[nf2 * 2 + 1][1], st + T_BL + off);
            }
            #pragma unroll
            for (int mf = 0; mf < 2; mf++)
                #pragma unroll
                for (int nf = 0; nf < 8; nf++) {
                    MMA_BF16(acc[mf][nf], ah[mf][0], ah[mf][1], ah[mf][2], ah[mf][3],
                             bh[nf][0], bh[nf][1]);
                    MMA_BF16(acc[mf][nf], ah[mf][0], ah[mf][1], ah[mf][2], ah[mf][3],
                             bl[nf][0], bl[nf][1]);
                    MMA_BF16(acc[mf][nf], al[mf][0], al[mf][1], al[mf][2], al[mf][3],
                             bh[nf][0], bh[nf][1]);
                }
        }
        __syncthreads();
    }

    #pragma unroll
    for (int mf = 0; mf < 2; mf++) {
        #pragma unroll
        for (int nf = 0; nf < 8; nf++) {
            const int col = ntile * 128 + wn + nf * 8 + (lane & 3) * 2;
            const int row0 = mtile * 128 + wm + mf * 16 + (lane >> 2);
            const float b0 = bias[col], b1 = bias[col + 1];
            float v0 = acc[mf][nf][0] + b0, v1 = acc[mf][nf][1] + b1;
            float v2 = acc[mf][nf][2] + b0, v3 = acc[mf][nf][3] + b1;
            if (OUTHL) {
                uint32_t h0, l0, h1, l1;
                pack_hl(v0, v1, h0, l0);
                pack_hl(v2, v3, h1, l1);
                *(uint32_t*)&Ch[(size_t)row0 * Ntot + col] = h0;
                *(uint32_t*)&Cl[(size_t)row0 * Ntot + col] = l0;
                *(uint32_t*)&Ch[(size_t)(row0 + 8) * Ntot + col] = h1;
                *(uint32_t*)&Cl[(size_t)(row0 + 8) * Ntot + col] = l1;
            } else {
                *(float2*)&Cf[(size_t)row0 * Ntot + col] = make_float2(v0, v1);
                *(float2*)&Cf[(size_t)(row0 + 8) * Ntot + col] = make_float2(v2, v3);
            }
        }
    }
}

// ===================== tensor-core causal flash attention ==================
// CTA: 128 q-rows x 1 head. 8 warps x 16 rows. Double-buffered K/V stages.
#define A_KH   0
#define A_KL   16384
#define A_VH   32768
#define A_VL   49152
#define A_BUF  65536
#define ATT_SMEM 131072
#define C1 0.18033688011112042f   // 0.125 * log2(e)

__device__ __forceinline__ void attn_load_kv(
    uint32_t bufbase,
    const __nv_bfloat16* qkvh, const __nv_bfloat16* qkvl,
    const __nv_bfloat16* vth, const __nv_bfloat16* vtl,
    int b, int h, int jt, int tid)
{
    // K tile: 128 rows x 64 bf16, hi/lo
    #pragma unroll
    for (int j = 0; j < 8; j++) {
        int idx = tid + j * 256;
        int hl = idx >> 10, r = (idx >> 3) & 127, c = idx & 7;
        const __nv_bfloat16* src = (hl ? qkvl : qkvh)
            + (size_t)(b * SEQ + jt * 128 + r) * N1 + DIM + h * HD + c * 8;
        CP16(bufbase + hl * 16384 + r * 128 + ((c ^ (r & 7)) << 4), src);
    }
    // V^T tile: 2 parts x 64 d-rows x 64 bf16 (k-contiguous), hi/lo
    #pragma unroll
    for (int j = 0; j < 8; j++) {
        int idx = tid + j * 256;
        int hl = idx >> 10, d = (idx >> 4) & 63, kc = idx & 15;
        int p = kc >> 3, c = kc & 7;
        const __nv_bfloat16* src = (hl ? vtl : vth)
            + (size_t)((b * NH + h) * HD + d) * SEQ + jt * 128 + kc * 8;
        CP16(bufbase + A_VH + hl * 16384 + p * 8192 + d * 128 + ((c ^ (d & 7)) << 4), src);
    }
}

__global__ __launch_bounds__(256, 1) void attn_mma(
    const __nv_bfloat16* __restrict__ qkvh, const __nv_bfloat16* __restrict__ qkvl,
    const __nv_bfloat16* __restrict__ vth, const __nv_bfloat16* __restrict__ vtl,
    __nv_bfloat16* __restrict__ oh, __nv_bfloat16* __restrict__ ol)
{
    extern __shared__ char smem[];
    const uint32_t sb = smem_u32(smem);
    const int tid = threadIdx.x, lane = tid & 31, w = tid >> 5;
    const int qt = blockIdx.x, h = blockIdx.y, b = blockIdx.z;
    const int nt = qt + 1;

    // ---- stage Q tile into buf0 K region, then to fragments ----
    #pragma unroll
    for (int j = 0; j < 8; j++) {
        int idx = tid + j * 256;
        int hl = idx >> 10, r = (idx >> 3) & 127, c = idx & 7;
        const __nv_bfloat16* src = (hl ? qkvl : qkvh)
            + (size_t)(b * SEQ + qt * 128 + r) * N1 + h * HD + c * 8;
        CP16(sb + hl * 16384 + r * 128 + ((c ^ (r & 7)) << 4), src);
    }
    CP_COMMIT(); CP_WAIT(0);
    __syncthreads();

    const int rowA = w * 16 + (lane & 15);
    const int clA = lane >> 4, xorA = rowA & 7;
    uint32_t qh[4][4], ql[4][4];
    #pragma unroll
    for (int ks = 0; ks < 4; ks++) {
        uint32_t off = (uint32_t)(rowA * 128 + ((((ks << 1) + clA) ^ xorA) << 4));
        LDSM4(qh[ks][0], qh[ks][1], qh[ks][2], qh[ks][3], sb + off);
        LDSM4(ql[ks][0], ql[ks][1], ql[ks][2], ql[ks][3], sb + 16384 + off);
    }
    __syncthreads();

    attn_load_kv(sb, qkvh, qkvl, vth, vtl, b, h, 0, tid);
    CP_COMMIT();

    float m2[2] = {-1e30f, -1e30f}, lsum[2] = {0.f, 0.f};
    float o[8][4];
    #pragma unroll
    for (int nf = 0; nf < 8; nf++)
        #pragma unroll
        for (int q = 0; q < 4; q++) o[nf][q] = 0.f;

    const int rowB = ((lane >> 4) << 3) + (lane & 7);
    const int clB = (lane >> 3) & 1, xorB = lane & 7;

    for (int jt = 0; jt < nt; jt++) {
        CP_WAIT(0);
        __syncthreads();
        if (jt + 1 < nt) {
            attn_load_kv(sb + ((jt + 1) & 1) * A_BUF, qkvh, qkvl, vth, vtl,
                         b, h, jt + 1, tid);
            CP_COMMIT();
        }
        const uint32_t kb = sb + (jt & 1) * A_BUF;

        // ---- scores S = Q K^T (128x128 per CTA, 16x128 per warp) ----
        float s[16][4];
        #pragma unroll
        for (int nf = 0; nf < 16; nf++)
            #pragma unroll
            for (int q = 0; q < 4; q++) s[nf][q] = 0.f;

        #pragma unroll
        for (int ks = 0; ks < 4; ks++) {
            #pragma unroll
            for (int nf2 = 0; nf2 < 8; nf2++) {
                uint32_t off = (uint32_t)((rowB + nf2 * 16) * 128 +
                               ((((ks << 1) + clB) ^ xorB) << 4));
                uint32_t kh0, kh1, kh2, kh3, kl0, kl1, kl2, kl3;
                LDSM4(kh0, kh1, kh2, kh3, kb + A_KH + off);
                LDSM4(kl0, kl1, kl2, kl3, kb + A_KL + off);
                MMA_BF16(s[nf2 * 2], qh[ks][0], qh[ks][1], qh[ks][2], qh[ks][3], kh0, kh1);
                MMA_BF16(s[nf2 * 2], qh[ks][0], qh[ks][1], qh[ks][2], qh[ks][3], kl0, kl1);
                MMA_BF16(s[nf2 * 2], ql[ks][0], ql[ks][1], ql[ks][2], ql[ks][3], kh0, kh1);
                MMA_BF16(s[nf2 * 2 + 1], qh[ks][0], qh[ks][1], qh[ks][2], qh[ks][3], kh2, kh3);
                MMA_BF16(s[nf2 * 2 + 1], qh[ks][0], qh[ks][1], qh[ks][2], qh[ks][3], kl2, kl3);
                MMA_BF16(s[nf2 * 2 + 1], ql[ks][0], ql[ks][1], ql[ks][2], ql[ks][3], kh2, kh3);
            }
        }

        // ---- causal mask (diagonal tile only) ----
        if (jt == qt) {
            const int r0l = w * 16 + (lane >> 2);
            #pragma unroll
            for (int nf = 0; nf < 16; nf++) {
                const int c0l = nf * 8 + (lane & 3) * 2;
                if (c0l     > r0l)     s[nf][0] = -3e38f;
                if (c0l + 1 > r0l)     s[nf][1] = -3e38f;
                if (c0l     > r0l + 8) s[nf][2] = -3e38f;
                if (c0l + 1 > r0l + 8) s[nf][3] = -3e38f;
            }
        }

        // ---- online softmax (base-2, scale folded into C1) ----
        float mx0 = -3e38f, mx1 = -3e38f;
        #pragma unroll
        for (int nf = 0; nf < 16; nf++) {
            mx0 = fmaxf(mx0, fmaxf(s[nf][0], s[nf][1]));
            mx1 = fmaxf(mx1, fmaxf(s[nf][2], s[nf][3]));
        }
        mx0 = fmaxf(mx0, __shfl_xor_sync(0xffffffffu, mx0, 1));
        mx0 = fmaxf(mx0, __shfl_xor_sync(0xffffffffu, mx0, 2));
        mx1 = fmaxf(mx1, __shfl_xor_sync(0xffffffffu, mx1, 1));
        mx1 = fmaxf(mx1, __shfl_xor_sync(0xffffffffu, mx1, 2));
        const float m2n0 = fmaxf(m2[0], mx0 * C1);
        const float m2n1 = fmaxf(m2[1], mx1 * C1);
        const float corr0 = exp2f(m2[0] - m2n0);
        const float corr1 = exp2f(m2[1] - m2n1);
        m2[0] = m2n0; m2[1] = m2n1;

        float rs0 = 0.f, rs1 = 0.f;
        #pragma unroll
        for (int nf = 0; nf < 16; nf++) {
            s[nf][0] = exp2f(fmaf(s[nf][0], C1, -m2n0)); rs0 += s[nf][0];
            s[nf][1] = exp2f(fmaf(s[nf][1], C1, -m2n0)); rs0 += s[nf][1];
            s[nf][2] = exp2f(fmaf(s[nf][2], C1, -m2n1)); rs1 += s[nf][2];
            s[nf][3] = exp2f(fmaf(s[nf][3], C1, -m2n1)); rs1 += s[nf][3];
        }
        rs0 += __shfl_xor_sync(0xffffffffu, rs0, 1);
        rs0 += __shfl_xor_sync(0xffffffffu, rs0, 2);
        rs1 += __shfl_xor_sync(0xffffffffu, rs1, 1);
        rs1 += __shfl_xor_sync(0xffffffffu, rs1, 2);
        lsum[0] = lsum[0] * corr0 + rs0;
        lsum[1] = lsum[1] * corr1 + rs1;
        #pragma unroll
        for (int nf = 0; nf < 8; nf++) {
            o[nf][0] *= corr0; o[nf][1] *= corr0;
            o[nf][2] *= corr1; o[nf][3] *= corr1;
        }

        // ---- O += P V  (P from score frags, V^T from smem) ----
        #pragma unroll
        for (int p = 0; p < 2; p++) {
            #pragma unroll
            for (int ks2 = 0; ks2 < 4; ks2++) {
                const int kc = p * 4 + ks2;
                uint32_t pa0, pa1, pa2, pa3, pb0, pb1, pb2, pb3;
                pack_hl(s[2 * kc][0],     s[2 * kc][1],     pa0, pb0);
                pack_hl(s[2 * kc][2],     s[2 * kc][3],     pa1, pb1);
                pack_hl(s[2 * kc + 1][0], s[2 * kc + 1][1], pa2, pb2);
                pack_hl(s[2 * kc + 1][2], s[2 * kc + 1][3], pa3, pb3);
                #pragma unroll
                for (int nf2 = 0; nf2 < 4; nf2++) {
                    uint32_t off = (uint32_t)(p * 8192 + (rowB + nf2 * 16) * 128 +
                                   ((((ks2 << 1) + clB) ^ xorB) << 4));
                    uint32_t vh0, vh1, vh2, vh3, vl0, vl1, vl2, vl3;
                    LDSM4(vh0, vh1, vh2, vh3, kb + A_VH + off);
                    LDSM4(vl0, vl1, vl2, vl3, kb + A_VL + off);
                    MMA_BF16(o[nf2 * 2], pa0, pa1, pa2, pa3, vh0, vh1);
                    MMA_BF16(o[nf2 * 2], pa0, pa1, pa2, pa3, vl0, vl1);
                    MMA_BF16(o[nf2 * 2], pb0, pb1, pb2, pb3, vh0, vh1);
                    MMA_BF16(o[nf2 * 2 + 1], pa0, pa1, pa2, pa3, vh2, vh3);
                    MMA_BF16(o[nf2 * 2 + 1], pa0, pa1, pa2, pa3, vl2, vl3);
                    MMA_BF16(o[nf2 * 2 + 1], pb0, pb1, pb2, pb3, vh2, vh3);
                }
            }
        }
    }

    // ---- normalize + write bf16 hi/lo ----
    const float inv0 = 1.f / lsum[0], inv1 = 1.f / lsum[1];
    const size_t gr = (size_t)(b * SEQ + qt * 128 + w * 16 + (lane >> 2));
    const int colb = h * HD + (lane & 3) * 2;
    #pragma unroll
    for (int nf = 0; nf < 8; nf++) {
        const int col = colb + nf * 8;
        uint32_t h0, l0, h1, l1;
        pack_hl(o[nf][0] * inv0, o[nf][1] * inv0, h0, l0);
        pack_hl(o[nf][2] * inv1, o[nf][3] * inv1, h1, l1);
        *(uint32_t*)&oh[gr * DIM + col] = h0;
        *(uint32_t*)&ol[gr * DIM + col] = l0;
        *(uint32_t*)&oh[(gr + 8) * DIM + col] = h1;
        *(uint32_t*)&ol[(gr + 8) * DIM + col] = l1;
    }
}

// =============================== launch ====================================
extern "C" void kernel_launch(void* const* d_in, const int* in_sizes, int n_in,
                              void* d_out, int out_size)
{
    const float* x      = (const float*)d_in[0];
    const float* W_attn = (const float*)d_in[1];
    const float* b_attn = (const float*)d_in[2];
    const float* W_proj = (const float*)d_in[3];
    const float* b_proj = (const float*)d_in[4];
    float* out = (float*)d_out;

    __nv_bfloat16 *qkvh, *qkvl, *vth, *vtl, *xh, *xl, *ahp, *alp, *wth, *wtl;
    cudaGetSymbolAddress((void**)&qkvh, g_qkvh);
    cudaGetSymbolAddress((void**)&qkvl, g_qkvl);
    cudaGetSymbolAddress((void**)&vth, g_vth);
    cudaGetSymbolAddress((void**)&vtl, g_vtl);
    cudaGetSymbolAddress((void**)&xh,  g_xh);
    cudaGetSymbolAddress((void**)&xl,  g_xl);
    cudaGetSymbolAddress((void**)&ahp, g_ah);
    cudaGetSymbolAddress((void**)&alp, g_al);
    cudaGetSymbolAddress((void**)&wth, g_wth);
    cudaGetSymbolAddress((void**)&wtl, g_wtl);

    static int attrs_set = 0;
    if (!attrs_set) {
        cudaFuncSetAttribute(gemm_mma<0>, cudaFuncAttributeMaxDynamicSharedMemorySize, GEMM_SMEM);
        cudaFuncSetAttribute(gemm_mma<1>, cudaFuncAttributeMaxDynamicSharedMemorySize, GEMM_SMEM);
        cudaFuncSetAttribute(attn_mma, cudaFuncAttributeMaxDynamicSharedMemorySize, ATT_SMEM);
        attrs_set = 1;
    }

    // 1) x -> bf16 hi/lo
    {
        int n4 = MROWS * KTOT / 4;
        split_fp32<<<(n4 + 255) / 256, 256>>>(x, xh, xl, n4);
    }
    // 2) W_attn -> transposed hi/lo
    transpose_split<<<dim3(N1 / 32, KTOT / 32), dim3(32, 8)>>>(W_attn, wth, wtl, KTOT, N1);
    // 3) qkv GEMM -> bf16 hi/lo
    gemm_mma<1><<<dim3(N1 / 128, MROWS / 128), 256, GEMM_SMEM>>>(
        xh, xl, wth, wtl, b_attn, nullptr, qkvh, qkvl, N1);
    // 4) V transpose
    vtrans<<<dim3(SEQ / 32, HD / 32, BATCH * NH), dim3(32, 8)>>>(qkvh, qkvl, vth, vtl);
    // 5) attention (tensor cores)
    attn_mma<<<dim3(SEQ / 128, NH, BATCH), 256, ATT_SMEM>>>(
        qkvh, qkvl, vth, vtl, ahp, alp);
    // 6) W_proj -> transposed hi/lo
    transpose_split<<<dim3(N2 / 32, KTOT / 32), dim3(32, 8)>>>(W_proj, wth, wtl, KTOT, N2);
    // 7) out GEMM (fp32 out)
    gemm_mma<0><<<dim3(N2 / 128, MROWS / 128), 256, GEMM_SMEM>>>(
        ahp, alp, wth, wtl, b_proj, out, nullptr, nullptr, N2);
}